// round 10
// baseline (speedup 1.0000x reference)
#include <cuda_runtime.h>
#include <cuda_bf16.h>

// ---------------------------------------------------------------------------
// AAconv: 3x (AugmentedConv + ReLU[first two]) + FC head.
// Shapes fixed: B=16, S=32 (HW=1024), DK=16, DV=4, NH=4 => dkh=4, dvh=1.
// Layers: (ci, co) = (8,32), (32,32), (32,6); conv_oc = co-4; qkv_oc = 36.
// ---------------------------------------------------------------------------

#define BATCH 16
#define HW 1024

// Scratch (device globals; allocation-free per harness rules).
__device__ __align__(16) float g_xA[BATCH * 32 * HW];
__device__ __align__(16) float g_xB[BATCH * 32 * HW];
__device__ __align__(16) float g_conv[BATCH * 2 * HW];  // layer2 conv branch
__device__ __align__(16) float g_qkv[BATCH * 36 * HW];  // qkv buffer
__device__ __align__(16) float g_attn[BATCH * 4 * HW];  // per-head attn out

// ---- packed f32x2 helpers (Blackwell FFMA2; ptxas won't auto-generate) ----
__device__ __forceinline__ unsigned long long pk2(float lo, float hi) {
    unsigned long long r;
    asm("mov.b64 %0, {%1, %2};" : "=l"(r) : "f"(lo), "f"(hi));
    return r;
}
__device__ __forceinline__ void upk2(unsigned long long v, float& lo, float& hi) {
    asm("mov.b64 {%0, %1}, %2;" : "=f"(lo), "=f"(hi) : "l"(v));
}
__device__ __forceinline__ unsigned long long fma2_(
    unsigned long long a, unsigned long long b, unsigned long long c) {
    unsigned long long r;
    asm("fma.rn.f32x2 %0, %1, %2, %3;" : "=l"(r) : "l"(a), "l"(b), "l"(c));
    return r;
}
__device__ __forceinline__ unsigned long long add2_(
    unsigned long long a, unsigned long long b) {
    unsigned long long r;
    asm("add.rn.f32x2 %0, %1, %2;" : "=l"(r) : "l"(a), "l"(b));
    return r;
}
__device__ __forceinline__ float ex2_(float x) {
    float r;
    asm("ex2.approx.ftz.f32 %0, %1;" : "=f"(r) : "f"(x));
    return r;
}

// ---------------------------------------------------------------------------
// Fused 3x3 conv: conv_out + qkv. Synchronous loader (round-7, measured
// best) + PACKED f32x2 compute: pixel pairs {px0,px1},{px2,px3} per oc,
// weights pre-duplicated {w,w} in smem (LDS.128 broadcast = 2 taps/load),
// input pairs built with 5 mov.b64 per row (alu pipe, offloads fma pipe).
// FFMA count per thread halves: 4608 -> 2304 fma2.
// Grid: (batch, oc-group-of-4, row-half). Block: 128 thr = 16 rows x 8 xq.
// out_sel: 0 -> g_conv (raw), 1 -> g_xA (ReLU), 2 -> g_xB (ReLU).
// in_sel:  0 -> in_ext,       1 -> g_xA,        2 -> g_xB.
// ---------------------------------------------------------------------------
__global__ __launch_bounds__(128) void conv_fused(
    const float* __restrict__ in_ext, int in_sel, int CI,
    const float* __restrict__ wc, const float* __restrict__ bc,
    int CO_CONV, int out_sel,
    const float* __restrict__ wq, const float* __restrict__ bq)
{
    const float* __restrict__ in =
        (in_sel == 0) ? in_ext : ((in_sel == 1) ? g_xA : g_xB);
    const int b    = blockIdx.x;
    const int oc0  = blockIdx.y * 4;
    const int half = blockIdx.z;
    const int OC_TOT = CO_CONV + 36;

    __shared__ __align__(16) float tile[8][18][36];
    __shared__ __align__(16) unsigned long long ws2[4][8][10]; // {w,w} pairs, taps 0..8 (+pad)
    __shared__ float wb[4];

    const int tid = threadIdx.x;
    if (tid < 4) {
        int oc = oc0 + tid;
        float bv = 0.f;
        if (oc < OC_TOT) bv = (oc < CO_CONV) ? bc[oc] : bq[oc - CO_CONV];
        wb[tid] = bv;
    }

    unsigned long long acc2[4][2];
#pragma unroll
    for (int o = 0; o < 4; o++) { acc2[o][0] = 0ull; acc2[o][1] = 0ull; }

    const int yl = tid >> 3;
    const int xh = tid & 7;
    const int xq = xh * 4;
    const int y  = half * 16 + yl;
    const int row0 = half * 16 - 1;

    for (int ci0 = 0; ci0 < CI; ci0 += 8) {
        // weights: 72 threads, each writes 4 oc packed {w,w} pairs
        if (tid < 72) {
            int c = tid / 9, tap = tid - c * 9;
#pragma unroll
            for (int o = 0; o < 4; o++) {
                int oc = oc0 + o;
                float val = 0.f;
                if (oc < OC_TOT) {
                    if (oc < CO_CONV) val = __ldg(wc + (oc * CI + ci0 + c) * 9 + tap);
                    else              val = __ldg(wq + ((oc - CO_CONV) * CI + ci0 + c) * 9 + tap);
                }
                ws2[o][c][tap] = pk2(val, val);
            }
        }
        // input strip: 8 ch x 18 rows x 32 cols, float4 vectorized (9 it/thr)
#pragma unroll
        for (int e = tid; e < 1152; e += 128) {
            int c  = e / 144;
            int r  = e - c * 144;
            int yy = r >> 3;
            int vx = (r & 7) << 2;
            int gy = row0 + yy;
            float4 v = make_float4(0.f, 0.f, 0.f, 0.f);
            if ((unsigned)gy < 32u)
                v = *reinterpret_cast<const float4*>(
                        in + ((b * CI + ci0 + c) << 10) + (gy << 5) + vx);
            *reinterpret_cast<float4*>(&tile[c][yy][vx]) = v;
        }
        __syncthreads();

#pragma unroll
        for (int c = 0; c < 8; c++) {
            // input cols xq-1 .. xq+4 -> 5 shifted pairs per row
            unsigned long long pr[3][5];
#pragma unroll
            for (int dy = 0; dy < 3; dy++) {
                const float* trow = tile[c][yl + dy];
                float4 mid = *reinterpret_cast<const float4*>(&trow[xq]);
                float p0 = (xh > 0) ? trow[xq - 1] : 0.f;
                float p5 = (xh < 7) ? trow[xq + 4] : 0.f;
                pr[dy][0] = pk2(p0,    mid.x);
                pr[dy][1] = pk2(mid.x, mid.y);
                pr[dy][2] = pk2(mid.y, mid.z);
                pr[dy][3] = pk2(mid.z, mid.w);
                pr[dy][4] = pk2(mid.w, p5);
            }
#pragma unroll
            for (int o = 0; o < 4; o++) {
                const unsigned long long* wp = ws2[o][c];
                ulonglong2 w01 = *reinterpret_cast<const ulonglong2*>(wp);      // taps 0,1
                ulonglong2 w23 = *reinterpret_cast<const ulonglong2*>(wp + 2);  // taps 2,3
                ulonglong2 w45 = *reinterpret_cast<const ulonglong2*>(wp + 4);  // taps 4,5
                ulonglong2 w67 = *reinterpret_cast<const ulonglong2*>(wp + 6);  // taps 6,7
                unsigned long long w8 = wp[8];
                unsigned long long a0 = acc2[o][0], a1 = acc2[o][1];
                // row 0: taps 0,1,2
                a0 = fma2_(w01.x, pr[0][0], a0);  a1 = fma2_(w01.x, pr[0][2], a1);
                a0 = fma2_(w01.y, pr[0][1], a0);  a1 = fma2_(w01.y, pr[0][3], a1);
                a0 = fma2_(w23.x, pr[0][2], a0);  a1 = fma2_(w23.x, pr[0][4], a1);
                // row 1: taps 3,4,5
                a0 = fma2_(w23.y, pr[1][0], a0);  a1 = fma2_(w23.y, pr[1][2], a1);
                a0 = fma2_(w45.x, pr[1][1], a0);  a1 = fma2_(w45.x, pr[1][3], a1);
                a0 = fma2_(w45.y, pr[1][2], a0);  a1 = fma2_(w45.y, pr[1][4], a1);
                // row 2: taps 6,7,8
                a0 = fma2_(w67.x, pr[2][0], a0);  a1 = fma2_(w67.x, pr[2][2], a1);
                a0 = fma2_(w67.y, pr[2][1], a0);  a1 = fma2_(w67.y, pr[2][3], a1);
                a0 = fma2_(w8,    pr[2][2], a0);  a1 = fma2_(w8,    pr[2][4], a1);
                acc2[o][0] = a0; acc2[o][1] = a1;
            }
        }
        __syncthreads();
    }

#pragma unroll
    for (int o = 0; o < 4; o++) {
        int oc = oc0 + o;
        if (oc >= OC_TOT) continue;
        float bv = wb[o];
        float a0, a1, a2, a3;
        upk2(acc2[o][0], a0, a1);
        upk2(acc2[o][1], a2, a3);
        float4 v4 = make_float4(a0 + bv, a1 + bv, a2 + bv, a3 + bv);
        float* dst;
        if (oc < CO_CONV) {
            if (out_sel == 0) {
                dst = g_conv + ((b * CO_CONV + oc) << 10);
            } else {
                v4.x = fmaxf(v4.x, 0.f); v4.y = fmaxf(v4.y, 0.f);
                v4.z = fmaxf(v4.z, 0.f); v4.w = fmaxf(v4.w, 0.f);
                dst = ((out_sel == 1) ? g_xA : g_xB) + ((b * 32 + oc) << 10);
            }
        } else {
            dst = g_qkv + ((b * 36 + (oc - CO_CONV)) << 10);
        }
        *reinterpret_cast<float4*>(dst + y * 32 + xq) = v4;
    }
}

// ---------------------------------------------------------------------------
// Attention (exact round-8 form — measured best, ~12us/layer):
// queries-in-lanes, packed-f32x2 key pairs, NO max subtraction.
// Block: 128 thr = 4 warps; warp = 32 queries (x warp-uniform, y = lane).
// ---------------------------------------------------------------------------
__global__ __launch_bounds__(128) void attn_kernel(
    const float* __restrict__ relw, const float* __restrict__ relh)
{
    const int chunk = blockIdx.x;  // 0..7 (128 queries each)
    const int n = blockIdx.y;      // head
    const int b = blockIdx.z;

    // ksp[xk][pair][8]: {k0_e,k0_o,k1_e,k1_o,k2_e,k2_o,k3_e,k3_o}
    __shared__ __align__(16) float ksp[32 * 128];
    __shared__ __align__(8)  float vs[1024];
    __shared__ float4 rws4[63];
    __shared__ float4 rhs4[63];

    const int tid = threadIdx.x;
    const float* kbase = g_qkv + ((size_t)(b * 36 + 16 + n * 4) << 10);
    const float* vbase = g_qkv + ((size_t)(b * 36 + 32 + n) << 10);
    for (int j = tid; j < 1024; j += 128) {
        int base = ((j >> 5) << 7) + (((j >> 1) & 15) << 3) + (j & 1);
        ksp[base + 0] = kbase[j];
        ksp[base + 2] = kbase[j + 1024];
        ksp[base + 4] = kbase[j + 2048];
        ksp[base + 6] = kbase[j + 3072];
        vs[j] = vbase[j];
    }
    if (tid < 63) {
        rws4[tid] = reinterpret_cast<const float4*>(relw)[tid];
        rhs4[tid] = reinterpret_cast<const float4*>(relh)[tid];
    }
    __syncthreads();

    const int warp = tid >> 5, lane = tid & 31;
    const int qbase0 = chunk * 128 + warp * 32;   // multiple of 32
    const int i = qbase0 + lane;
    const int x = qbase0 >> 5;                    // warp-uniform
    // y = lane

    const float* qptr = g_qkv + ((size_t)(b * 36 + n * 4) << 10);
    const float C = 0.7213475204444817f;          // 0.5 * log2(e)
    const float q0 = qptr[i]        * C;
    const float q1 = qptr[i + 1024] * C;
    const float q2 = qptr[i + 2048] * C;
    const float q3 = qptr[i + 3072] * C;

    const unsigned long long q00 = pk2(q0, q0);
    const unsigned long long q11 = pk2(q1, q1);
    const unsigned long long q22 = pk2(q2, q2);
    const unsigned long long q33 = pk2(q3, q3);

    // RW pairs: RW[yk] = q . rel_w[yk - lane + 31], packed {even, odd}
    unsigned long long RW2[16];
#pragma unroll
    for (int t = 0; t < 16; t++) {
        float4 rA = rws4[2 * t - lane + 31];
        float4 rB = rws4[2 * t + 1 - lane + 31];
        float w0 = fmaf(q0, rA.x, fmaf(q1, rA.y, fmaf(q2, rA.z, q3 * rA.w)));
        float w1 = fmaf(q0, rB.x, fmaf(q1, rB.y, fmaf(q2, rB.z, q3 * rB.w)));
        RW2[t] = pk2(w0, w1);
    }

    unsigned long long l2 = 0ull, a2 = 0ull;      // packed {even,odd} accum
    for (int xk = 0; xk < 32; xk++) {
        float4 rh = rhs4[xk - x + 31];            // broadcast
        float RH = fmaf(q0, rh.x, fmaf(q1, rh.y, fmaf(q2, rh.z, q3 * rh.w)));
        unsigned long long RH2 = pk2(RH, RH);
        const float* kp = &ksp[xk << 7];
        const float* vp = &vs[xk << 5];
#pragma unroll
        for (int t = 0; t < 16; t++) {
            ulonglong2 KA = *reinterpret_cast<const ulonglong2*>(kp + (t << 3));
            ulonglong2 KB = *reinterpret_cast<const ulonglong2*>(kp + (t << 3) + 4);
            unsigned long long s2 = add2_(RH2, RW2[t]);
            s2 = fma2_(q00, KA.x, s2);
            s2 = fma2_(q11, KA.y, s2);
            s2 = fma2_(q22, KB.x, s2);
            s2 = fma2_(q33, KB.y, s2);
            float s0, s1; upk2(s2, s0, s1);
            unsigned long long p2 = pk2(ex2_(s0), ex2_(s1));
            l2 = add2_(l2, p2);
            unsigned long long v2 = *reinterpret_cast<const unsigned long long*>(vp + (t << 1));
            a2 = fma2_(p2, v2, a2);
        }
    }
    float l0, l1, a0, a1;
    upk2(l2, l0, l1);
    upk2(a2, a0, a1);
    g_attn[((b * 4 + n) << 10) + i] = (a0 + a1) / (l0 + l1);
}

// ---------------------------------------------------------------------------
// Attn-only combine: 1x1 conv over 4 heads + ReLU -> 4 channels of g_x?.
// ---------------------------------------------------------------------------
__global__ __launch_bounds__(256) void combine_attn(
    const float* __restrict__ attn_w, const float* __restrict__ attn_b,
    int co_conv, int out_sel)
{
    int idx = blockIdx.x * 256 + threadIdx.x;
    if (idx >= BATCH * HW) return;
    int b = idx >> 10, i = idx & 1023;
    float a0 = g_attn[((b * 4 + 0) << 10) + i];
    float a1 = g_attn[((b * 4 + 1) << 10) + i];
    float a2 = g_attn[((b * 4 + 2) << 10) + i];
    float a3 = g_attn[((b * 4 + 3) << 10) + i];
    float* xout = (out_sel == 1) ? g_xA : g_xB;
#pragma unroll
    for (int cc = 0; cc < 4; cc++) {
        float v = attn_b[cc] + attn_w[cc * 4] * a0 + attn_w[cc * 4 + 1] * a1
                + attn_w[cc * 4 + 2] * a2 + attn_w[cc * 4 + 3] * a3;
        xout[((b * 32 + co_conv + cc) << 10) + i] = fmaxf(v, 0.f);
    }
}

// ---------------------------------------------------------------------------
// Final: layer2 concat (co_conv=2, raw in g_conv) + 1x1 attn conv + FC(6->1).
// ---------------------------------------------------------------------------
__global__ __launch_bounds__(256) void final_kernel(
    const float* __restrict__ attn_w, const float* __restrict__ attn_b,
    const float* __restrict__ fc_w, const float* __restrict__ fc_b,
    float* __restrict__ out)
{
    int idx = blockIdx.x * 256 + threadIdx.x;
    if (idx >= BATCH * HW) return;
    int b = idx >> 10, i = idx & 1023;
    float r = fc_b[0];
    r = fmaf(fc_w[0], g_conv[((b * 2 + 0) << 10) + i], r);
    r = fmaf(fc_w[1], g_conv[((b * 2 + 1) << 10) + i], r);
    float a0 = g_attn[((b * 4 + 0) << 10) + i];
    float a1 = g_attn[((b * 4 + 1) << 10) + i];
    float a2 = g_attn[((b * 4 + 2) << 10) + i];
    float a3 = g_attn[((b * 4 + 3) << 10) + i];
#pragma unroll
    for (int c = 0; c < 4; c++) {
        float v = attn_b[c] + attn_w[c * 4] * a0 + attn_w[c * 4 + 1] * a1
                + attn_w[c * 4 + 2] * a2 + attn_w[c * 4 + 3] * a3;
        r = fmaf(fc_w[2 + c], v, r);
    }
    out[idx] = r;
}

// ---------------------------------------------------------------------------
// Launch: inputs in metadata order:
// 0:x, per layer l: [1+8l..8+8l] = conv_w, conv_b, qkv_w, qkv_b,
//                                  attn_w, attn_b, relw, relh; 25:fc_w, 26:fc_b
// ---------------------------------------------------------------------------
extern "C" void kernel_launch(void* const* d_in, const int* in_sizes, int n_in,
                              void* d_out, int out_size)
{
    (void)in_sizes; (void)n_in; (void)out_size;
    const float* x = (const float*)d_in[0];
    auto L = [&](int l, int k) { return (const float*)d_in[1 + l * 8 + k]; };
    float* out = (float*)d_out;
    const int PIX_BLKS = (BATCH * HW + 255) / 256;

    // ---- layer 0: ci=8, conv_oc=28 -> g_xA (ReLU) ----
    conv_fused<<<dim3(16, 16, 2), 128>>>(x, 0, 8, L(0, 0), L(0, 1), 28, 1, L(0, 2), L(0, 3));
    attn_kernel<<<dim3(8, 4, 16), 128>>>(L(0, 6), L(0, 7));
    combine_attn<<<PIX_BLKS, 256>>>(L(0, 4), L(0, 5), 28, 1);

    // ---- layer 1: ci=32 (g_xA), conv_oc=28 -> g_xB (ReLU) ----
    conv_fused<<<dim3(16, 16, 2), 128>>>(nullptr, 1, 32, L(1, 0), L(1, 1), 28, 2, L(1, 2), L(1, 3));
    attn_kernel<<<dim3(8, 4, 16), 128>>>(L(1, 6), L(1, 7));
    combine_attn<<<PIX_BLKS, 256>>>(L(1, 4), L(1, 5), 28, 2);

    // ---- layer 2: ci=32 (g_xB), conv_oc=2 -> g_conv (raw) ----
    conv_fused<<<dim3(16, 10, 2), 128>>>(nullptr, 2, 32, L(2, 0), L(2, 1), 2, 0, L(2, 2), L(2, 3));
    attn_kernel<<<dim3(8, 4, 16), 128>>>(L(2, 6), L(2, 7));
    final_kernel<<<PIX_BLKS, 256>>>(
        L(2, 4), L(2, 5), (const float*)d_in[25], (const float*)d_in[26], out);
}

// round 11
// speedup vs baseline: 1.1072x; 1.1072x over previous
#include <cuda_runtime.h>
#include <cuda_bf16.h>

// ---------------------------------------------------------------------------
// AAconv: 3x (AugmentedConv + ReLU[first two]) + FC head.
// Shapes fixed: B=16, S=32 (HW=1024), DK=16, DV=4, NH=4 => dkh=4, dvh=1.
// Layers: (ci, co) = (8,32), (32,32), (32,6); conv_oc = co-4; qkv_oc = 36.
//
// Structure per layer (single stream, overlap inside one launch):
//   1) qkv_conv_kernel  : 3x3 conv -> 36 qkv channels only (9 oc-groups)
//   2) attn_conv_kernel : FAT kernel = 512 attn blocks + conv-branch blocks
//                         (attention and conv-branch channels run concurrently)
//   3) combine_attn     : 1x1 conv over heads + ReLU -> attn channels of g_x
// ---------------------------------------------------------------------------

#define BATCH 16
#define HW 1024
#define SMEM_BYTES 23040

// Scratch (device globals; allocation-free per harness rules).
__device__ __align__(16) float g_xA[BATCH * 32 * HW];
__device__ __align__(16) float g_xB[BATCH * 32 * HW];
__device__ __align__(16) float g_conv[BATCH * 2 * HW];  // layer2 conv branch
__device__ __align__(16) float g_qkv[BATCH * 36 * HW];  // qkv buffer
__device__ __align__(16) float g_attn[BATCH * 4 * HW];  // per-head attn out

// ---- packed f32x2 helpers (Blackwell FFMA2; ptxas won't auto-generate) ----
__device__ __forceinline__ unsigned long long pk2(float lo, float hi) {
    unsigned long long r;
    asm("mov.b64 %0, {%1, %2};" : "=l"(r) : "f"(lo), "f"(hi));
    return r;
}
__device__ __forceinline__ void upk2(unsigned long long v, float& lo, float& hi) {
    asm("mov.b64 {%0, %1}, %2;" : "=f"(lo), "=f"(hi) : "l"(v));
}
__device__ __forceinline__ unsigned long long fma2_(
    unsigned long long a, unsigned long long b, unsigned long long c) {
    unsigned long long r;
    asm("fma.rn.f32x2 %0, %1, %2, %3;" : "=l"(r) : "l"(a), "l"(b), "l"(c));
    return r;
}
__device__ __forceinline__ unsigned long long add2_(
    unsigned long long a, unsigned long long b) {
    unsigned long long r;
    asm("add.rn.f32x2 %0, %1, %2;" : "=l"(r) : "l"(a), "l"(b));
    return r;
}
__device__ __forceinline__ float ex2_(float x) {
    float r;
    asm("ex2.approx.ftz.f32 %0, %1;" : "=f"(r) : "f"(x));
    return r;
}

// ---------------------------------------------------------------------------
// Conv body (verbatim round-7 math — measured best 27.4us @ CI=32 full conv).
// Computes oc group [oc0, oc0+4) masked to oc < OC_LIM. Block: 128 thr.
// Smem overlay (dynamic): tile @0 (20736B), ws @20736 (1536B), wb @22272.
// out_sel: 0 -> g_conv (raw), 1 -> g_xA (ReLU), 2 -> g_xB (ReLU).
// ---------------------------------------------------------------------------
__device__ __forceinline__ void conv_body(
    const float* __restrict__ in, int CI,
    const float* __restrict__ wc, const float* __restrict__ bc, int CO_CONV,
    const float* __restrict__ wq, const float* __restrict__ bq,
    int OC_LIM, int out_sel, int b, int oc0, int half, char* sm)
{
    float (*tile)[18][36] = reinterpret_cast<float (*)[18][36]>(sm);
    float (*ws)[8][12]    = reinterpret_cast<float (*)[8][12]>(sm + 20736);
    float* wb             = reinterpret_cast<float*>(sm + 22272);

    const int tid = threadIdx.x;
    if (tid < 4) {
        int oc = oc0 + tid;
        float bv = 0.f;
        if (oc < OC_LIM) bv = (oc < CO_CONV) ? bc[oc] : bq[oc - CO_CONV];
        wb[tid] = bv;
    }

    float acc[4][4];
#pragma unroll
    for (int o = 0; o < 4; o++)
#pragma unroll
        for (int p = 0; p < 4; p++) acc[o][p] = 0.f;

    const int yl = tid >> 3;
    const int xh = tid & 7;
    const int xq = xh * 4;
    const int y  = half * 16 + yl;
    const int row0 = half * 16 - 1;

    for (int ci0 = 0; ci0 < CI; ci0 += 8) {
        if (tid < 72) {
            int c = tid / 9, tap = tid - c * 9;
#pragma unroll
            for (int o = 0; o < 4; o++) {
                int oc = oc0 + o;
                float val = 0.f;
                if (oc < OC_LIM) {
                    if (oc < CO_CONV) val = __ldg(wc + (oc * CI + ci0 + c) * 9 + tap);
                    else              val = __ldg(wq + ((oc - CO_CONV) * CI + ci0 + c) * 9 + tap);
                }
                ws[o][c][tap] = val;
            }
        }
#pragma unroll
        for (int e = tid; e < 1152; e += 128) {
            int c  = e / 144;
            int r  = e - c * 144;
            int yy = r >> 3;
            int vx = (r & 7) << 2;
            int gy = row0 + yy;
            float4 v = make_float4(0.f, 0.f, 0.f, 0.f);
            if ((unsigned)gy < 32u)
                v = *reinterpret_cast<const float4*>(
                        in + ((b * CI + ci0 + c) << 10) + (gy << 5) + vx);
            *reinterpret_cast<float4*>(&tile[c][yy][vx]) = v;
        }
        __syncthreads();

#pragma unroll
        for (int c = 0; c < 8; c++) {
            float p[3][6];
#pragma unroll
            for (int dy = 0; dy < 3; dy++) {
                const float* trow = tile[c][yl + dy];
                float4 mid = *reinterpret_cast<const float4*>(&trow[xq]);
                p[dy][0] = (xh > 0) ? trow[xq - 1] : 0.f;
                p[dy][1] = mid.x; p[dy][2] = mid.y;
                p[dy][3] = mid.z; p[dy][4] = mid.w;
                p[dy][5] = (xh < 7) ? trow[xq + 4] : 0.f;
            }
#pragma unroll
            for (int o = 0; o < 4; o++) {
                float4 wA = *reinterpret_cast<const float4*>(&ws[o][c][0]);
                float4 wB = *reinterpret_cast<const float4*>(&ws[o][c][4]);
                float  w8 = ws[o][c][8];
#pragma unroll
                for (int px = 0; px < 4; px++) {
                    float a = acc[o][px];
                    a = fmaf(wA.x, p[0][px], a);
                    a = fmaf(wA.y, p[0][px + 1], a);
                    a = fmaf(wA.z, p[0][px + 2], a);
                    a = fmaf(wA.w, p[1][px], a);
                    a = fmaf(wB.x, p[1][px + 1], a);
                    a = fmaf(wB.y, p[1][px + 2], a);
                    a = fmaf(wB.z, p[2][px], a);
                    a = fmaf(wB.w, p[2][px + 1], a);
                    a = fmaf(w8,   p[2][px + 2], a);
                    acc[o][px] = a;
                }
            }
        }
        __syncthreads();
    }

#pragma unroll
    for (int o = 0; o < 4; o++) {
        int oc = oc0 + o;
        if (oc >= OC_LIM) continue;
        float bv = wb[o];
        float4 v4 = make_float4(acc[o][0] + bv, acc[o][1] + bv,
                                acc[o][2] + bv, acc[o][3] + bv);
        float* dst;
        if (oc < CO_CONV) {
            if (out_sel == 0) {
                dst = g_conv + ((b * CO_CONV + oc) << 10);
            } else {
                v4.x = fmaxf(v4.x, 0.f); v4.y = fmaxf(v4.y, 0.f);
                v4.z = fmaxf(v4.z, 0.f); v4.w = fmaxf(v4.w, 0.f);
                dst = ((out_sel == 1) ? g_xA : g_xB) + ((b * 32 + oc) << 10);
            }
        } else {
            dst = g_qkv + ((b * 36 + (oc - CO_CONV)) << 10);
        }
        *reinterpret_cast<float4*>(dst + y * 32 + xq) = v4;
    }
}

// ---------------------------------------------------------------------------
// Attention body (verbatim round-8 — measured best): queries-in-lanes,
// packed-f32x2 key pairs, NO max subtraction. 128 thr = 4 warps.
// Smem overlay: ksp @0 (16384B), vs @16384 (4096B), rws4 @20480, rhs4 @21488.
// ---------------------------------------------------------------------------
__device__ __forceinline__ void attn_body(
    const float* __restrict__ relw, const float* __restrict__ relh,
    int chunk, int n, int b, char* sm)
{
    float*  ksp  = reinterpret_cast<float*>(sm);
    float*  vs   = reinterpret_cast<float*>(sm + 16384);
    float4* rws4 = reinterpret_cast<float4*>(sm + 20480);
    float4* rhs4 = reinterpret_cast<float4*>(sm + 21488);

    const int tid = threadIdx.x;
    const float* kbase = g_qkv + ((size_t)(b * 36 + 16 + n * 4) << 10);
    const float* vbase = g_qkv + ((size_t)(b * 36 + 32 + n) << 10);
    for (int j = tid; j < 1024; j += 128) {
        int base = ((j >> 5) << 7) + (((j >> 1) & 15) << 3) + (j & 1);
        ksp[base + 0] = kbase[j];
        ksp[base + 2] = kbase[j + 1024];
        ksp[base + 4] = kbase[j + 2048];
        ksp[base + 6] = kbase[j + 3072];
        vs[j] = vbase[j];
    }
    if (tid < 63) {
        rws4[tid] = reinterpret_cast<const float4*>(relw)[tid];
        rhs4[tid] = reinterpret_cast<const float4*>(relh)[tid];
    }
    __syncthreads();

    const int warp = tid >> 5, lane = tid & 31;
    const int qbase0 = chunk * 128 + warp * 32;   // multiple of 32
    const int i = qbase0 + lane;
    const int x = qbase0 >> 5;                    // warp-uniform
    // y = lane

    const float* qptr = g_qkv + ((size_t)(b * 36 + n * 4) << 10);
    const float C = 0.7213475204444817f;          // 0.5 * log2(e)
    const float q0 = qptr[i]        * C;
    const float q1 = qptr[i + 1024] * C;
    const float q2 = qptr[i + 2048] * C;
    const float q3 = qptr[i + 3072] * C;

    const unsigned long long q00 = pk2(q0, q0);
    const unsigned long long q11 = pk2(q1, q1);
    const unsigned long long q22 = pk2(q2, q2);
    const unsigned long long q33 = pk2(q3, q3);

    unsigned long long RW2[16];
#pragma unroll
    for (int t = 0; t < 16; t++) {
        float4 rA = rws4[2 * t - lane + 31];
        float4 rB = rws4[2 * t + 1 - lane + 31];
        float w0 = fmaf(q0, rA.x, fmaf(q1, rA.y, fmaf(q2, rA.z, q3 * rA.w)));
        float w1 = fmaf(q0, rB.x, fmaf(q1, rB.y, fmaf(q2, rB.z, q3 * rB.w)));
        RW2[t] = pk2(w0, w1);
    }

    unsigned long long l2 = 0ull, a2 = 0ull;      // packed {even,odd} accum
    for (int xk = 0; xk < 32; xk++) {
        float4 rh = rhs4[xk - x + 31];            // broadcast
        float RH = fmaf(q0, rh.x, fmaf(q1, rh.y, fmaf(q2, rh.z, q3 * rh.w)));
        unsigned long long RH2 = pk2(RH, RH);
        const float* kp = &ksp[xk << 7];
        const float* vp = &vs[xk << 5];
#pragma unroll
        for (int t = 0; t < 16; t++) {
            ulonglong2 KA = *reinterpret_cast<const ulonglong2*>(kp + (t << 3));
            ulonglong2 KB = *reinterpret_cast<const ulonglong2*>(kp + (t << 3) + 4);
            unsigned long long s2 = add2_(RH2, RW2[t]);
            s2 = fma2_(q00, KA.x, s2);
            s2 = fma2_(q11, KA.y, s2);
            s2 = fma2_(q22, KB.x, s2);
            s2 = fma2_(q33, KB.y, s2);
            float s0, s1; upk2(s2, s0, s1);
            unsigned long long p2 = pk2(ex2_(s0), ex2_(s1));
            l2 = add2_(l2, p2);
            unsigned long long v2 = *reinterpret_cast<const unsigned long long*>(vp + (t << 1));
            a2 = fma2_(p2, v2, a2);
        }
    }
    float l0, l1, a0, a1;
    upk2(l2, l0, l1);
    upk2(a2, a0, a1);
    g_attn[((b * 4 + n) << 10) + i] = (a0 + a1) / (l0 + l1);
}

// ---------------------------------------------------------------------------
// Kernel 1: qkv channels only (oc in [CO_CONV, CO_CONV+36), 9 groups of 4).
// Grid: (batch, 9, 2).
// ---------------------------------------------------------------------------
__global__ __launch_bounds__(128) void qkv_conv_kernel(
    const float* __restrict__ in_ext, int in_sel, int CI,
    const float* __restrict__ wc, const float* __restrict__ bc, int CO_CONV,
    const float* __restrict__ wq, const float* __restrict__ bq)
{
    extern __shared__ char sm[];
    const float* in = (in_sel == 0) ? in_ext : ((in_sel == 1) ? g_xA : g_xB);
    conv_body(in, CI, wc, bc, CO_CONV, wq, bq, CO_CONV + 36, /*out_sel*/0,
              blockIdx.x, CO_CONV + blockIdx.y * 4, blockIdx.z, sm);
}

// ---------------------------------------------------------------------------
// Kernel 2 (FAT): blocks [0,512) run attention; blocks >= 512 run the
// conv-branch oc groups (oc < CO_CONV). They execute concurrently.
// ---------------------------------------------------------------------------
__global__ __launch_bounds__(128) void attn_conv_kernel(
    const float* __restrict__ in_ext, int in_sel, int CI,
    const float* __restrict__ wc, const float* __restrict__ bc,
    int CO_CONV, int out_sel,
    const float* __restrict__ relw, const float* __restrict__ relh)
{
    extern __shared__ char sm[];
    const int bid = blockIdx.x;
    if (bid < 512) {
        attn_body(relw, relh, bid & 7, (bid >> 3) & 3, bid >> 5, sm);
    } else {
        const int cid  = bid - 512;
        const int half = cid & 1;
        const int rest = cid >> 1;
        const int b    = rest & 15;
        const int grp  = rest >> 4;
        const float* in = (in_sel == 0) ? in_ext : ((in_sel == 1) ? g_xA : g_xB);
        conv_body(in, CI, wc, bc, CO_CONV, wc, bc, /*OC_LIM=*/CO_CONV,
                  out_sel, b, grp * 4, half, sm);
    }
}

// ---------------------------------------------------------------------------
// Attn-only combine: 1x1 conv over 4 heads + ReLU -> 4 channels of g_x?.
// ---------------------------------------------------------------------------
__global__ __launch_bounds__(256) void combine_attn(
    const float* __restrict__ attn_w, const float* __restrict__ attn_b,
    int co_conv, int out_sel)
{
    int idx = blockIdx.x * 256 + threadIdx.x;
    if (idx >= BATCH * HW) return;
    int b = idx >> 10, i = idx & 1023;
    float a0 = g_attn[((b * 4 + 0) << 10) + i];
    float a1 = g_attn[((b * 4 + 1) << 10) + i];
    float a2 = g_attn[((b * 4 + 2) << 10) + i];
    float a3 = g_attn[((b * 4 + 3) << 10) + i];
    float* xout = (out_sel == 1) ? g_xA : g_xB;
#pragma unroll
    for (int cc = 0; cc < 4; cc++) {
        float v = attn_b[cc] + attn_w[cc * 4] * a0 + attn_w[cc * 4 + 1] * a1
                + attn_w[cc * 4 + 2] * a2 + attn_w[cc * 4 + 3] * a3;
        xout[((b * 32 + co_conv + cc) << 10) + i] = fmaxf(v, 0.f);
    }
}

// ---------------------------------------------------------------------------
// Final: layer2 concat (co_conv=2, raw in g_conv) + 1x1 attn conv + FC(6->1).
// ---------------------------------------------------------------------------
__global__ __launch_bounds__(256) void final_kernel(
    const float* __restrict__ attn_w, const float* __restrict__ attn_b,
    const float* __restrict__ fc_w, const float* __restrict__ fc_b,
    float* __restrict__ out)
{
    int idx = blockIdx.x * 256 + threadIdx.x;
    if (idx >= BATCH * HW) return;
    int b = idx >> 10, i = idx & 1023;
    float r = fc_b[0];
    r = fmaf(fc_w[0], g_conv[((b * 2 + 0) << 10) + i], r);
    r = fmaf(fc_w[1], g_conv[((b * 2 + 1) << 10) + i], r);
    float a0 = g_attn[((b * 4 + 0) << 10) + i];
    float a1 = g_attn[((b * 4 + 1) << 10) + i];
    float a2 = g_attn[((b * 4 + 2) << 10) + i];
    float a3 = g_attn[((b * 4 + 3) << 10) + i];
#pragma unroll
    for (int c = 0; c < 4; c++) {
        float v = attn_b[c] + attn_w[c * 4] * a0 + attn_w[c * 4 + 1] * a1
                + attn_w[c * 4 + 2] * a2 + attn_w[c * 4 + 3] * a3;
        r = fmaf(fc_w[2 + c], v, r);
    }
    out[idx] = r;
}

// ---------------------------------------------------------------------------
// Launch: inputs in metadata order:
// 0:x, per layer l: [1+8l..8+8l] = conv_w, conv_b, qkv_w, qkv_b,
//                                  attn_w, attn_b, relw, relh; 25:fc_w, 26:fc_b
// ---------------------------------------------------------------------------
extern "C" void kernel_launch(void* const* d_in, const int* in_sizes, int n_in,
                              void* d_out, int out_size)
{
    (void)in_sizes; (void)n_in; (void)out_size;
    const float* x = (const float*)d_in[0];
    auto L = [&](int l, int k) { return (const float*)d_in[1 + l * 8 + k]; };
    float* out = (float*)d_out;
    const int PIX_BLKS = (BATCH * HW + 255) / 256;

    // ---- layer 0: ci=8, conv_oc=28 -> g_xA (ReLU); branch = 7 groups ----
    qkv_conv_kernel<<<dim3(16, 9, 2), 128, SMEM_BYTES>>>(
        x, 0, 8, L(0, 0), L(0, 1), 28, L(0, 2), L(0, 3));
    attn_conv_kernel<<<512 + 7 * 32, 128, SMEM_BYTES>>>(
        x, 0, 8, L(0, 0), L(0, 1), 28, 1, L(0, 6), L(0, 7));
    combine_attn<<<PIX_BLKS, 256>>>(L(0, 4), L(0, 5), 28, 1);

    // ---- layer 1: ci=32 (g_xA), conv_oc=28 -> g_xB (ReLU) ----
    qkv_conv_kernel<<<dim3(16, 9, 2), 128, SMEM_BYTES>>>(
        nullptr, 1, 32, L(1, 0), L(1, 1), 28, L(1, 2), L(1, 3));
    attn_conv_kernel<<<512 + 7 * 32, 128, SMEM_BYTES>>>(
        nullptr, 1, 32, L(1, 0), L(1, 1), 28, 2, L(1, 6), L(1, 7));
    combine_attn<<<PIX_BLKS, 256>>>(L(1, 4), L(1, 5), 28, 2);

    // ---- layer 2: ci=32 (g_xB), conv_oc=2 -> g_conv (raw); branch = 1 group ----
    qkv_conv_kernel<<<dim3(16, 9, 2), 128, SMEM_BYTES>>>(
        nullptr, 2, 32, L(2, 0), L(2, 1), 2, L(2, 2), L(2, 3));
    attn_conv_kernel<<<512 + 1 * 32, 128, SMEM_BYTES>>>(
        nullptr, 2, 32, L(2, 0), L(2, 1), 2, 0, L(2, 6), L(2, 7));
    final_kernel<<<PIX_BLKS, 256>>>(
        L(2, 4), L(2, 5), (const float*)d_in[25], (const float*)d_in[26], out);
}

// round 12
// speedup vs baseline: 1.1569x; 1.0449x over previous
#include <cuda_runtime.h>
#include <cuda_bf16.h>

// ---------------------------------------------------------------------------
// AAconv: 3x (AugmentedConv + ReLU[first two]) + FC head.
// Shapes fixed: B=16, S=32 (HW=1024), DK=16, DV=4, NH=4 => dkh=4, dvh=1.
// Layers: (ci, co) = (8,32), (32,32), (32,6); conv_oc = co-4; qkv_oc = 36.
//
// Per layer: conv_fused_t<CI> (all oc groups, 16-ch chunks) then attn_fused
// (all 4 heads + 1x1 combine / final FC in one kernel, 128 blocks).
// ---------------------------------------------------------------------------

#define BATCH 16
#define HW 1024

// attn_fused dynamic smem layout
#define A_KSP   0               // 4 heads x 4096 floats (interleaved pairs)
#define A_VS    65536           // 4 heads x 1024 floats
#define A_RWS   81920           // 63 float4
#define A_RHS   82928           // 63 float4
#define A_RES   83936           // 128 x 5 floats (stride-5: conflict-free)
#define ATTN_SMEM (83936 + 2560)

// Scratch (device globals; allocation-free per harness rules).
__device__ __align__(16) float g_xA[BATCH * 32 * HW];
__device__ __align__(16) float g_xB[BATCH * 32 * HW];
__device__ __align__(16) float g_conv[BATCH * 2 * HW];  // layer2 conv branch
__device__ __align__(16) float g_qkv[BATCH * 36 * HW];  // qkv buffer

// ---- packed f32x2 helpers (Blackwell FFMA2; ptxas won't auto-generate) ----
__device__ __forceinline__ unsigned long long pk2(float lo, float hi) {
    unsigned long long r;
    asm("mov.b64 %0, {%1, %2};" : "=l"(r) : "f"(lo), "f"(hi));
    return r;
}
__device__ __forceinline__ void upk2(unsigned long long v, float& lo, float& hi) {
    asm("mov.b64 {%0, %1}, %2;" : "=f"(lo), "=f"(hi) : "l"(v));
}
__device__ __forceinline__ unsigned long long fma2_(
    unsigned long long a, unsigned long long b, unsigned long long c) {
    unsigned long long r;
    asm("fma.rn.f32x2 %0, %1, %2, %3;" : "=l"(r) : "l"(a), "l"(b), "l"(c));
    return r;
}
__device__ __forceinline__ unsigned long long add2_(
    unsigned long long a, unsigned long long b) {
    unsigned long long r;
    asm("add.rn.f32x2 %0, %1, %2;" : "=l"(r) : "l"(a), "l"(b));
    return r;
}
__device__ __forceinline__ float ex2_(float x) {
    float r;
    asm("ex2.approx.ftz.f32 %0, %1;" : "=f"(r) : "f"(x));
    return r;
}

// ---------------------------------------------------------------------------
// Fused 3x3 conv (round-7 math, 16-channel chunks => half the serial
// load/sync phases; 18 LDG.128 in flight per phase). Computes conv_out
// (CO_CONV ch) + qkv (36 ch). Grid: (batch, oc-group-of-4, row-half).
// Block: 128 thr = 16 rows x 8 xq; 4 oc x 4 px accumulators.
// out_sel: 0 -> g_conv (raw), 1 -> g_xA (ReLU), 2 -> g_xB (ReLU).
// in_sel:  0 -> in_ext,       1 -> g_xA,        2 -> g_xB.
// ---------------------------------------------------------------------------
template <int CI>
__global__ __launch_bounds__(128) void conv_fused_t(
    const float* __restrict__ in_ext, int in_sel,
    const float* __restrict__ wc, const float* __restrict__ bc,
    int CO_CONV, int out_sel,
    const float* __restrict__ wq, const float* __restrict__ bq)
{
    constexpr int CC  = (CI < 16) ? CI : 16;   // channels per chunk
    constexpr int NCH = CI / CC;               // chunks

    const float* __restrict__ in =
        (in_sel == 0) ? in_ext : ((in_sel == 1) ? g_xA : g_xB);
    const int b    = blockIdx.x;
    const int oc0  = blockIdx.y * 4;
    const int half = blockIdx.z;
    const int OC_TOT = CO_CONV + 36;

    __shared__ __align__(16) float tile[CC][18][36];
    __shared__ __align__(16) float ws[4][CC][12];
    __shared__ float wb[4];

    const int tid = threadIdx.x;
    if (tid < 4) {
        int oc = oc0 + tid;
        float bv = 0.f;
        if (oc < OC_TOT) bv = (oc < CO_CONV) ? bc[oc] : bq[oc - CO_CONV];
        wb[tid] = bv;
    }

    float acc[4][4];
#pragma unroll
    for (int o = 0; o < 4; o++)
#pragma unroll
        for (int p = 0; p < 4; p++) acc[o][p] = 0.f;

    const int yl = tid >> 3;
    const int xh = tid & 7;
    const int xq = xh * 4;
    const int y  = half * 16 + yl;
    const int row0 = half * 16 - 1;

    for (int k = 0; k < NCH; k++) {
        const int ci0 = k * CC;
        // weights: 72 threads cover (c mod 8, tap); loop c by 8
        if (tid < 72) {
            int c0 = tid / 9, tap = tid - c0 * 9;
#pragma unroll
            for (int cb = 0; cb < CC; cb += 8) {
                int c = c0 + cb;
#pragma unroll
                for (int o = 0; o < 4; o++) {
                    int oc = oc0 + o;
                    float val = 0.f;
                    if (oc < OC_TOT) {
                        if (oc < CO_CONV) val = __ldg(wc + (oc * CI + ci0 + c) * 9 + tap);
                        else              val = __ldg(wq + ((oc - CO_CONV) * CI + ci0 + c) * 9 + tap);
                    }
                    ws[o][c][tap] = val;
                }
            }
        }
        // input strip: CC ch x 18 rows x 32 cols, float4 vectorized
#pragma unroll
        for (int e = tid; e < CC * 144; e += 128) {
            int c  = e / 144;
            int r  = e - c * 144;
            int yy = r >> 3;
            int vx = (r & 7) << 2;
            int gy = row0 + yy;
            float4 v = make_float4(0.f, 0.f, 0.f, 0.f);
            if ((unsigned)gy < 32u)
                v = *reinterpret_cast<const float4*>(
                        in + ((b * CI + ci0 + c) << 10) + (gy << 5) + vx);
            *reinterpret_cast<float4*>(&tile[c][yy][vx]) = v;
        }
        __syncthreads();

#pragma unroll 8
        for (int c = 0; c < CC; c++) {
            float p[3][6];
#pragma unroll
            for (int dy = 0; dy < 3; dy++) {
                const float* trow = tile[c][yl + dy];
                float4 mid = *reinterpret_cast<const float4*>(&trow[xq]);
                p[dy][0] = (xh > 0) ? trow[xq - 1] : 0.f;
                p[dy][1] = mid.x; p[dy][2] = mid.y;
                p[dy][3] = mid.z; p[dy][4] = mid.w;
                p[dy][5] = (xh < 7) ? trow[xq + 4] : 0.f;
            }
#pragma unroll
            for (int o = 0; o < 4; o++) {
                float4 wA = *reinterpret_cast<const float4*>(&ws[o][c][0]);
                float4 wB = *reinterpret_cast<const float4*>(&ws[o][c][4]);
                float  w8 = ws[o][c][8];
#pragma unroll
                for (int px = 0; px < 4; px++) {
                    float a = acc[o][px];
                    a = fmaf(wA.x, p[0][px], a);
                    a = fmaf(wA.y, p[0][px + 1], a);
                    a = fmaf(wA.z, p[0][px + 2], a);
                    a = fmaf(wA.w, p[1][px], a);
                    a = fmaf(wB.x, p[1][px + 1], a);
                    a = fmaf(wB.y, p[1][px + 2], a);
                    a = fmaf(wB.z, p[2][px], a);
                    a = fmaf(wB.w, p[2][px + 1], a);
                    a = fmaf(w8,   p[2][px + 2], a);
                    acc[o][px] = a;
                }
            }
        }
        if (k + 1 < NCH) __syncthreads();
    }

#pragma unroll
    for (int o = 0; o < 4; o++) {
        int oc = oc0 + o;
        if (oc >= OC_TOT) continue;
        float bv = wb[o];
        float4 v4 = make_float4(acc[o][0] + bv, acc[o][1] + bv,
                                acc[o][2] + bv, acc[o][3] + bv);
        float* dst;
        if (oc < CO_CONV) {
            if (out_sel == 0) {
                dst = g_conv + ((b * CO_CONV + oc) << 10);
            } else {
                v4.x = fmaxf(v4.x, 0.f); v4.y = fmaxf(v4.y, 0.f);
                v4.z = fmaxf(v4.z, 0.f); v4.w = fmaxf(v4.w, 0.f);
                dst = ((out_sel == 1) ? g_xA : g_xB) + ((b * 32 + oc) << 10);
            }
        } else {
            dst = g_qkv + ((b * 36 + (oc - CO_CONV)) << 10);
        }
        *reinterpret_cast<float4*>(dst + y * 32 + xq) = v4;
    }
}

// ---------------------------------------------------------------------------
// attn_fused: ALL 4 heads of one (chunk, batch) + 1x1 combine in one block.
// Grid (8, 16) = 128 blocks (single wave). 512 thr = 4 warpgroups, one per
// head; warp-level math is verbatim round-8 (queries-in-lanes, f32x2 pairs,
// no max subtraction). Heads exchange via stride-5 smem staging; threads
// 0..127 then apply the 1x1 attn conv:
//   out_sel 1/2 -> ReLU into g_xA/g_xB channels [co_conv, co_conv+4)
//   out_sel 0   -> final: concat with g_conv (2 ch) + FC(6->1) -> out
// ---------------------------------------------------------------------------
__global__ __launch_bounds__(512) void attn_fused(
    const float* __restrict__ relw, const float* __restrict__ relh,
    const float* __restrict__ attn_w, const float* __restrict__ attn_b,
    const float* __restrict__ fc_w, const float* __restrict__ fc_b,
    float* __restrict__ out, int co_conv, int out_sel)
{
    extern __shared__ char sm[];
    float*  ksp  = reinterpret_cast<float*>(sm + A_KSP);  // [4][4096]
    float*  vs   = reinterpret_cast<float*>(sm + A_VS);   // [4][1024]
    float4* rws4 = reinterpret_cast<float4*>(sm + A_RWS);
    float4* rhs4 = reinterpret_cast<float4*>(sm + A_RHS);
    float*  res  = reinterpret_cast<float*>(sm + A_RES);  // [128][5]

    const int chunk = blockIdx.x;  // 0..7 (128 queries each)
    const int b     = blockIdx.y;
    const int tid   = threadIdx.x;

    // loader: K (interleaved pairs) + V for all 4 heads; rel tables
    for (int j = tid; j < 4096; j += 512) {
        int h  = j >> 10, jj = j & 1023;
        const float* kb = g_qkv + ((size_t)(b * 36 + 16 + h * 4) << 10);
        int base = h * 4096 + ((jj >> 5) << 7) + (((jj >> 1) & 15) << 3) + (jj & 1);
        ksp[base + 0] = kb[jj];
        ksp[base + 2] = kb[jj + 1024];
        ksp[base + 4] = kb[jj + 2048];
        ksp[base + 6] = kb[jj + 3072];
        vs[h * 1024 + jj] = g_qkv[((size_t)(b * 36 + 32 + h) << 10) + jj];
    }
    if (tid < 63) rws4[tid] = reinterpret_cast<const float4*>(relw)[tid];
    if (tid >= 64 && tid < 127) rhs4[tid - 64] = reinterpret_cast<const float4*>(relh)[tid - 64];
    __syncthreads();

    const int n      = tid >> 7;        // head (warpgroup)
    const int wg_tid = tid & 127;
    const int wig    = wg_tid >> 5;     // query group within chunk
    const int lane   = wg_tid & 31;
    const int qbase0 = chunk * 128 + wig * 32;
    const int i      = qbase0 + lane;
    const int x      = qbase0 >> 5;     // warp-uniform
    // y = lane

    const float* qptr = g_qkv + ((size_t)(b * 36 + n * 4) << 10);
    const float C = 0.7213475204444817f;          // 0.5 * log2(e)
    const float q0 = qptr[i]        * C;
    const float q1 = qptr[i + 1024] * C;
    const float q2 = qptr[i + 2048] * C;
    const float q3 = qptr[i + 3072] * C;

    const unsigned long long q00 = pk2(q0, q0);
    const unsigned long long q11 = pk2(q1, q1);
    const unsigned long long q22 = pk2(q2, q2);
    const unsigned long long q33 = pk2(q3, q3);

    unsigned long long RW2[16];
#pragma unroll
    for (int t = 0; t < 16; t++) {
        float4 rA = rws4[2 * t - lane + 31];
        float4 rB = rws4[2 * t + 1 - lane + 31];
        float w0 = fmaf(q0, rA.x, fmaf(q1, rA.y, fmaf(q2, rA.z, q3 * rA.w)));
        float w1 = fmaf(q0, rB.x, fmaf(q1, rB.y, fmaf(q2, rB.z, q3 * rB.w)));
        RW2[t] = pk2(w0, w1);
    }

    unsigned long long l2 = 0ull, a2 = 0ull;      // packed {even,odd} accum
    const float* kh = ksp + n * 4096;
    const float* vh = vs + n * 1024;
    for (int xk = 0; xk < 32; xk++) {
        float4 rh = rhs4[xk - x + 31];            // broadcast
        float RH = fmaf(q0, rh.x, fmaf(q1, rh.y, fmaf(q2, rh.z, q3 * rh.w)));
        unsigned long long RH2 = pk2(RH, RH);
        const float* kp = kh + (xk << 7);
        const float* vp = vh + (xk << 5);
#pragma unroll
        for (int t = 0; t < 16; t++) {
            ulonglong2 KA = *reinterpret_cast<const ulonglong2*>(kp + (t << 3));
            ulonglong2 KB = *reinterpret_cast<const ulonglong2*>(kp + (t << 3) + 4);
            unsigned long long s2 = add2_(RH2, RW2[t]);
            s2 = fma2_(q00, KA.x, s2);
            s2 = fma2_(q11, KA.y, s2);
            s2 = fma2_(q22, KB.x, s2);
            s2 = fma2_(q33, KB.y, s2);
            float s0, s1; upk2(s2, s0, s1);
            unsigned long long p2 = pk2(ex2_(s0), ex2_(s1));
            l2 = add2_(l2, p2);
            unsigned long long v2 = *reinterpret_cast<const unsigned long long*>(vp + (t << 1));
            a2 = fma2_(p2, v2, a2);
        }
    }
    float l0, l1, a0, a1;
    upk2(l2, l0, l1);
    upk2(a2, a0, a1);
    res[(wig * 32 + lane) * 5 + n] = (a0 + a1) / (l0 + l1);
    __syncthreads();

    // combine: 1x1 conv over heads (+ ReLU -> g_x, or FC -> out)
    if (tid < 128) {
        const int i2 = chunk * 128 + tid;
        float h0 = res[tid * 5 + 0];
        float h1 = res[tid * 5 + 1];
        float h2 = res[tid * 5 + 2];
        float h3 = res[tid * 5 + 3];
        if (out_sel == 0) {
            float r = fc_b[0];
            r = fmaf(fc_w[0], g_conv[((b * 2 + 0) << 10) + i2], r);
            r = fmaf(fc_w[1], g_conv[((b * 2 + 1) << 10) + i2], r);
#pragma unroll
            for (int c = 0; c < 4; c++) {
                float v = attn_b[c] + attn_w[c * 4] * h0 + attn_w[c * 4 + 1] * h1
                        + attn_w[c * 4 + 2] * h2 + attn_w[c * 4 + 3] * h3;
                r = fmaf(fc_w[2 + c], v, r);
            }
            out[(b << 10) + i2] = r;
        } else {
            float* xout = (out_sel == 1) ? g_xA : g_xB;
#pragma unroll
            for (int cc = 0; cc < 4; cc++) {
                float v = attn_b[cc] + attn_w[cc * 4] * h0 + attn_w[cc * 4 + 1] * h1
                        + attn_w[cc * 4 + 2] * h2 + attn_w[cc * 4 + 3] * h3;
                xout[((b * 32 + co_conv + cc) << 10) + i2] = fmaxf(v, 0.f);
            }
        }
    }
}

// ---------------------------------------------------------------------------
// Launch: inputs in metadata order:
// 0:x, per layer l: [1+8l..8+8l] = conv_w, conv_b, qkv_w, qkv_b,
//                                  attn_w, attn_b, relw, relh; 25:fc_w, 26:fc_b
// ---------------------------------------------------------------------------
extern "C" void kernel_launch(void* const* d_in, const int* in_sizes, int n_in,
                              void* d_out, int out_size)
{
    (void)in_sizes; (void)n_in; (void)out_size;
    const float* x = (const float*)d_in[0];
    auto L = [&](int l, int k) { return (const float*)d_in[1 + l * 8 + k]; };
    float* out = (float*)d_out;

    static bool attr_set = false;
    if (!attr_set) {
        cudaFuncSetAttribute(attn_fused,
                             cudaFuncAttributeMaxDynamicSharedMemorySize,
                             ATTN_SMEM);
        attr_set = true;
    }

    // ---- layer 0: ci=8, conv_oc=28 -> g_xA (ReLU); 16 oc groups ----
    conv_fused_t<8><<<dim3(16, 16, 2), 128>>>(
        x, 0, L(0, 0), L(0, 1), 28, 1, L(0, 2), L(0, 3));
    attn_fused<<<dim3(8, 16), 512, ATTN_SMEM>>>(
        L(0, 6), L(0, 7), L(0, 4), L(0, 5), nullptr, nullptr, nullptr, 28, 1);

    // ---- layer 1: ci=32 (g_xA), conv_oc=28 -> g_xB (ReLU) ----
    conv_fused_t<32><<<dim3(16, 16, 2), 128>>>(
        nullptr, 1, L(1, 0), L(1, 1), 28, 2, L(1, 2), L(1, 3));
    attn_fused<<<dim3(8, 16), 512, ATTN_SMEM>>>(
        L(1, 6), L(1, 7), L(1, 4), L(1, 5), nullptr, nullptr, nullptr, 28, 2);

    // ---- layer 2: ci=32 (g_xB), conv_oc=2 -> g_conv (raw); 10 oc groups ----
    conv_fused_t<32><<<dim3(16, 10, 2), 128>>>(
        nullptr, 2, L(2, 0), L(2, 1), 2, 0, L(2, 2), L(2, 3));
    attn_fused<<<dim3(8, 16), 512, ATTN_SMEM>>>(
        L(2, 6), L(2, 7), L(2, 4), L(2, 5),
        (const float*)d_in[25], (const float*)d_in[26], out, 2, 0);
}